// round 6
// baseline (speedup 1.0000x reference)
#include <cuda_runtime.h>
#include <cuda_bf16.h>

// SimpleLSS: softmax over depth sums to 1 -> weighted == img_feat.
// Whole op == bilinear upsample (24,256,16,44) -> (24,256,128,128).
//
// R6: R2 skeleton + Blackwell 256-bit stores (st.global.cs.v8.f32).
// Halves store instruction count, doubles burst width per STG, keeps
// the proven high-occupancy direct-store dataflow.

#define IN_H 16
#define IN_W 44
#define OUT_HW 128
#define PLANE_IN (IN_H * IN_W)       // 704
#define PLANE_OUT (OUT_HW * OUT_HW)  // 16384

__global__ __launch_bounds__(256) void lss_resize_kernel(
    const float* __restrict__ img, float* __restrict__ out)
{
    const int plane = blockIdx.x;                 // n*256 + c
    const float* __restrict__ src = img + (long long)plane * PLANE_IN;
    float* __restrict__ dst = out + (long long)plane * PLANE_OUT;

    __shared__ float tile[PLANE_IN];          // raw 16x44 input
    __shared__ float hrow[IN_H * OUT_HW];     // 16x128 horizontally-interp'd

    // ---- stage 0: load input plane (704 floats) ----
    for (int i = threadIdx.x; i < PLANE_IN; i += 256)
        tile[i] = src[i];
    __syncthreads();

    // ---- stage 1: horizontal interp, 2048 values, 8/thread ----
    #pragma unroll
    for (int k = 0; k < 8; ++k) {
        const int i = k * 256 + threadIdx.x;
        const int r = i >> 7;            // input row 0..15
        const int x = i & 127;           // output col 0..127
        // horizontal scale 44/128 = 0.34375 (exact fp32)
        float sx = fmaxf(((float)x + 0.5f) * 0.34375f - 0.5f, 0.0f);
        int   x0 = (int)sx;
        float fx = sx - (float)x0;
        int   x1 = min(x0 + 1, IN_W - 1);
        const float* rp = tile + r * IN_W;
        float v0 = rp[x0];
        hrow[i] = v0 + fx * (rp[x1] - v0);
    }
    __syncthreads();

    // ---- stage 2: vertical blend, 8 floats/thread/iter, STG.256 ----
    #pragma unroll
    for (int it = 0; it < 8; ++it) {
        const int l = it * 2048 + threadIdx.x * 8;  // output linear idx
        const int y = l >> 7;
        const int x = l & 127;

        // vertical scale 16/128 = 0.125
        float sy = fmaxf(((float)y + 0.5f) * 0.125f - 0.5f, 0.0f);
        int   y0 = (int)sy;
        float fy = sy - (float)y0;
        int   y1 = min(y0 + 1, IN_H - 1);

        const float4* A = reinterpret_cast<const float4*>(hrow + y0 * OUT_HW + x);
        const float4* B = reinterpret_cast<const float4*>(hrow + y1 * OUT_HW + x);
        float4 a0 = A[0], a1 = A[1];
        float4 b0 = B[0], b1 = B[1];

        float v0 = a0.x + fy * (b0.x - a0.x);
        float v1 = a0.y + fy * (b0.y - a0.y);
        float v2 = a0.z + fy * (b0.z - a0.z);
        float v3 = a0.w + fy * (b0.w - a0.w);
        float v4 = a1.x + fy * (b1.x - a1.x);
        float v5 = a1.y + fy * (b1.y - a1.y);
        float v6 = a1.z + fy * (b1.z - a1.z);
        float v7 = a1.w + fy * (b1.w - a1.w);

        // 256-bit streaming store (sm_100+)
        asm volatile(
            "st.global.cs.v8.f32 [%0], {%1,%2,%3,%4,%5,%6,%7,%8};"
            :: "l"(dst + l),
               "f"(v0), "f"(v1), "f"(v2), "f"(v3),
               "f"(v4), "f"(v5), "f"(v6), "f"(v7)
            : "memory");
    }
}

extern "C" void kernel_launch(void* const* d_in, const int* in_sizes, int n_in,
                              void* d_out, int out_size)
{
    const float* img = (const float*)d_in[0];   // (24,256,16,44)
    float* out = (float*)d_out;                 // (24,256,128,128)
    const int planes = in_sizes[0] / PLANE_IN;  // 6144
    lss_resize_kernel<<<planes, 256>>>(img, out);
}